// round 10
// baseline (speedup 1.0000x reference)
#include <cuda_runtime.h>
#include <cuda_bf16.h>

// Problem constants
constexpr int NB   = 16;
constexpr int CIN  = 256;
constexpr int COUT = 256;
constexpr int HH   = 64;
constexpr int WWp  = 64;
constexpr int HWp  = HH * WWp;          // 4096
constexpr int NPIX = NB * HWp;          // 65536
constexpr int KT   = CIN * 9;           // 2304

// GEMM tiling
constexpr int BM = 128;                 // out channels per block
constexpr int BN = 128;                 // pixels per block
constexpr int BK = 8;
constexpr int KTILES = KT / BK;         // 288

// Scratch (static device memory — no allocations)
__device__ float g_h1[NB * COUT * HWp];   // intermediate after conv1 (~67 MB)
__device__ float g_mask[NPIX];            // binary mask (std)
__device__ float g_maskd[NPIX];           // dilated mask (3x3 maxpool)

// ---------------------------------------------------------------------------
// Kernel 1: mask = (conv1x1(x, w_mask) + b > 0) ? 1 : 0
// ---------------------------------------------------------------------------
__global__ void mask_kernel(const float* __restrict__ x,
                            const float* __restrict__ wm,
                            const float* __restrict__ bm)
{
    __shared__ float sw[CIN];
    const int t = threadIdx.x;
    sw[t] = wm[t];
    __syncthreads();

    const int p  = blockIdx.x * 256 + t;     // 0..65535
    const int n  = p >> 12;
    const int hw = p & 4095;
    const float* xp = x + n * (CIN * HWp) + hw;

    float s = bm[0];
#pragma unroll 8
    for (int c = 0; c < CIN; ++c)
        s = fmaf(xp[c * HWp], sw[c], s);

    g_mask[p] = (s > 0.0f) ? 1.0f : 0.0f;
}

// ---------------------------------------------------------------------------
// Kernel 2: mask_dilate = 3x3 maxpool(mask), SAME
// ---------------------------------------------------------------------------
__global__ void dilate_kernel()
{
    const int p  = blockIdx.x * 256 + threadIdx.x;
    const int n  = p >> 12;
    const int hw = p & 4095;
    const int h  = hw >> 6;
    const int w  = hw & 63;
    const float* m = g_mask + n * HWp;

    float v = 0.0f;
#pragma unroll
    for (int dy = -1; dy <= 1; ++dy) {
        const int hh = h + dy;
        if ((unsigned)hh >= (unsigned)HH) continue;
#pragma unroll
        for (int dx = -1; dx <= 1; ++dx) {
            const int ww = w + dx;
            if ((unsigned)ww >= (unsigned)WWp) continue;
            v = fmaxf(v, m[hh * WWp + ww]);
        }
    }
    g_maskd[p] = v;
}

// ---------------------------------------------------------------------------
// Kernel 3/4: 3x3 conv as implicit GEMM, 128x128x8 tiles, double-buffered smem.
//   EPI==0: in = x,     gate = mask_dilate, out = g_h1   (relu(conv*gate))
//   EPI==1: in = g_h1,  gate = mask,        out = d_out  (x + relu(conv*gate)*gate)
// ---------------------------------------------------------------------------
template <int EPI>
__global__ __launch_bounds__(256, 2)
void conv3x3_kernel(const float* __restrict__ xp,     // x (input for EPI=0, residual for EPI=1)
                    const float* __restrict__ wt,     // weights [256][2304] row-major
                    float* __restrict__ op)           // d_out (used when EPI=1)
{
    const float* xin  = (EPI == 0) ? xp : (const float*)g_h1;
    const float* gate = (EPI == 0) ? (const float*)g_maskd : (const float*)g_mask;
    float*       out  = (EPI == 0) ? (float*)g_h1 : op;

    __shared__ float As[2][BK][BM];
    __shared__ float Bs[2][BK][BN];

    const int t    = threadIdx.x;
    const int tx   = t & 15;          // pixel group (8 px)
    const int ty   = t >> 4;          // oc group (8 oc)
    const int pix0 = blockIdx.x * BN; // 128-pixel block: one image, two full rows
    const int oc0  = blockIdx.y * BM;
    const int n    = pix0 >> 12;
    const int hw0  = pix0 & 4095;
    const int h0   = hw0 >> 6;

    const float* xn = xin + n * (CIN * HWp);

    // A (weights) load mapping: thread -> one float4 of W row
    const int am = t >> 1;            // 0..127 : local oc
    const int ak = (t & 1) * 4;       // 0 or 4 : k offset within BK
    // B (im2col input) load mapping: thread -> 4 consecutive pixels of one k-row
    const int bk  = t >> 5;           // 0..7 : local k
    const int bp  = (t & 31) * 4;     // 0..124 : local pixel (4-aligned, same row)
    const int b_h = h0 + (bp >> 6);
    const int b_w = bp & 63;

    float acc[8][8];
#pragma unroll
    for (int i = 0; i < 8; ++i)
#pragma unroll
        for (int j = 0; j < 8; ++j) acc[i][j] = 0.0f;

    float4 areg;
    float  breg[4];

    // ---- load tile 0 ----
    {
        areg = *(const float4*)(wt + (oc0 + am) * KT + 0 + ak);
        const int kg = 0 + bk;
        const int c  = kg / 9;
        const int r  = kg - c * 9;
        const int ky = r / 3;
        const int dy = ky - 1;
        const int dx = (r - ky * 3) - 1;
        const int hh = b_h + dy;
        const bool rowok = (unsigned)hh < (unsigned)HH;
        const float* rowp = xn + c * HWp + hh * WWp;
#pragma unroll
        for (int j = 0; j < 4; ++j) {
            const int ww = b_w + dx + j;
            breg[j] = (rowok && (unsigned)ww < (unsigned)WWp) ? rowp[ww] : 0.0f;
        }
        As[0][ak + 0][am] = areg.x;
        As[0][ak + 1][am] = areg.y;
        As[0][ak + 2][am] = areg.z;
        As[0][ak + 3][am] = areg.w;
        *(float4*)&Bs[0][bk][bp] = make_float4(breg[0], breg[1], breg[2], breg[3]);
    }
    __syncthreads();

    int buf = 0;
    for (int kt = 0; kt < KTILES; ++kt) {
        const bool has_next = (kt + 1) < KTILES;
        if (has_next) {
            const int k0 = (kt + 1) * BK;
            areg = *(const float4*)(wt + (oc0 + am) * KT + k0 + ak);
            const int kg = k0 + bk;
            const int c  = kg / 9;
            const int r  = kg - c * 9;
            const int ky = r / 3;
            const int dy = ky - 1;
            const int dx = (r - ky * 3) - 1;
            const int hh = b_h + dy;
            const bool rowok = (unsigned)hh < (unsigned)HH;
            const float* rowp = xn + c * HWp + hh * WWp;
#pragma unroll
            for (int j = 0; j < 4; ++j) {
                const int ww = b_w + dx + j;
                breg[j] = (rowok && (unsigned)ww < (unsigned)WWp) ? rowp[ww] : 0.0f;
            }
        }

        // ---- compute on current buffer ----
#pragma unroll
        for (int k = 0; k < BK; ++k) {
            const float4 a0 = *(const float4*)&As[buf][k][ty * 8];
            const float4 a1 = *(const float4*)&As[buf][k][ty * 8 + 4];
            const float4 b0 = *(const float4*)&Bs[buf][k][tx * 8];
            const float4 b1 = *(const float4*)&Bs[buf][k][tx * 8 + 4];
            const float av[8] = {a0.x, a0.y, a0.z, a0.w, a1.x, a1.y, a1.z, a1.w};
            const float bv[8] = {b0.x, b0.y, b0.z, b0.w, b1.x, b1.y, b1.z, b1.w};
#pragma unroll
            for (int i = 0; i < 8; ++i)
#pragma unroll
                for (int j = 0; j < 8; ++j)
                    acc[i][j] = fmaf(av[i], bv[j], acc[i][j]);
        }

        if (has_next) {
            const int nb = buf ^ 1;
            As[nb][ak + 0][am] = areg.x;
            As[nb][ak + 1][am] = areg.y;
            As[nb][ak + 2][am] = areg.z;
            As[nb][ak + 3][am] = areg.w;
            *(float4*)&Bs[nb][bk][bp] = make_float4(breg[0], breg[1], breg[2], breg[3]);
        }
        __syncthreads();
        buf ^= 1;
    }

    // ---- epilogue ----
    const int pbase = hw0 + tx * 8;
    const float4 g0 = *(const float4*)(gate + pix0 + tx * 8);
    const float4 g1 = *(const float4*)(gate + pix0 + tx * 8 + 4);
    const float gv[8] = {g0.x, g0.y, g0.z, g0.w, g1.x, g1.y, g1.z, g1.w};

#pragma unroll
    for (int i = 0; i < 8; ++i) {
        const int oc = oc0 + ty * 8 + i;
        float* po = out + ((n * COUT + oc) * HWp + pbase);
        if (EPI == 0) {
            float4 v0, v1;
            v0.x = fmaxf(acc[i][0] * gv[0], 0.0f);
            v0.y = fmaxf(acc[i][1] * gv[1], 0.0f);
            v0.z = fmaxf(acc[i][2] * gv[2], 0.0f);
            v0.w = fmaxf(acc[i][3] * gv[3], 0.0f);
            v1.x = fmaxf(acc[i][4] * gv[4], 0.0f);
            v1.y = fmaxf(acc[i][5] * gv[5], 0.0f);
            v1.z = fmaxf(acc[i][6] * gv[6], 0.0f);
            v1.w = fmaxf(acc[i][7] * gv[7], 0.0f);
            *(float4*)po       = v0;
            *(float4*)(po + 4) = v1;
        } else {
            const float* pr = xp + ((n * CIN + oc) * HWp + pbase);
            const float4 r0 = *(const float4*)pr;
            const float4 r1 = *(const float4*)(pr + 4);
            float4 v0, v1;
            v0.x = r0.x + fmaxf(acc[i][0] * gv[0], 0.0f) * gv[0];
            v0.y = r0.y + fmaxf(acc[i][1] * gv[1], 0.0f) * gv[1];
            v0.z = r0.z + fmaxf(acc[i][2] * gv[2], 0.0f) * gv[2];
            v0.w = r0.w + fmaxf(acc[i][3] * gv[3], 0.0f) * gv[3];
            v1.x = r1.x + fmaxf(acc[i][4] * gv[4], 0.0f) * gv[4];
            v1.y = r1.y + fmaxf(acc[i][5] * gv[5], 0.0f) * gv[5];
            v1.z = r1.z + fmaxf(acc[i][6] * gv[6], 0.0f) * gv[6];
            v1.w = r1.w + fmaxf(acc[i][7] * gv[7], 0.0f) * gv[7];
            *(float4*)po       = v0;
            *(float4*)(po + 4) = v1;
        }
    }
}

// ---------------------------------------------------------------------------
extern "C" void kernel_launch(void* const* d_in, const int* in_sizes, int n_in,
                              void* d_out, int out_size)
{
    const float* x  = (const float*)d_in[0];   // [16,256,64,64]
    const float* w1 = (const float*)d_in[1];   // [256,256,3,3]
    const float* w2 = (const float*)d_in[2];   // [256,256,3,3]
    const float* wm = (const float*)d_in[3];   // [1,256,1,1]
    const float* bm = (const float*)d_in[4];   // [1]
    float* out = (float*)d_out;

    mask_kernel<<<NPIX / 256, 256>>>(x, wm, bm);
    dilate_kernel<<<NPIX / 256, 256>>>();

    dim3 grid(NPIX / BN, COUT / BM);           // (512, 2)
    conv3x3_kernel<0><<<grid, 256>>>(x, w1, out);   // -> g_h1 (out arg unused)
    conv3x3_kernel<1><<<grid, 256>>>(x, w2, out);   // g_h1 -> out, residual x
}

// round 11
// speedup vs baseline: 1.0039x; 1.0039x over previous
#include <cuda_runtime.h>
#include <cuda_bf16.h>

// Problem constants
constexpr int NB   = 16;
constexpr int CIN  = 256;
constexpr int COUT = 256;
constexpr int HH   = 64;
constexpr int WWp  = 64;
constexpr int HWp  = HH * WWp;          // 4096
constexpr int NPIX = NB * HWp;          // 65536
constexpr int KT   = CIN * 9;           // 2304

// GEMM tiling
constexpr int BM = 128;                 // out channels per block
constexpr int BN = 128;                 // pixels per block
constexpr int BK = 8;
constexpr int KTILES = KT / BK;         // 288

// Scratch (static device memory — no allocations)
__device__ float g_h1[NB * COUT * HWp];   // intermediate after conv1 (~67 MB)
__device__ float g_mask[NPIX];            // binary mask (std)
__device__ float g_maskd[NPIX];           // dilated mask (3x3 maxpool)

// ---------------------------------------------------------------------------
// Kernel 1: mask = (conv1x1(x, w_mask) + b > 0) ? 1 : 0
// ---------------------------------------------------------------------------
__global__ void mask_kernel(const float* __restrict__ x,
                            const float* __restrict__ wm,
                            const float* __restrict__ bm)
{
    __shared__ float sw[CIN];
    const int t = threadIdx.x;
    sw[t] = wm[t];
    __syncthreads();

    const int p  = blockIdx.x * 256 + t;     // 0..65535
    const int n  = p >> 12;
    const int hw = p & 4095;
    const float* xp = x + n * (CIN * HWp) + hw;

    float s = bm[0];
#pragma unroll 8
    for (int c = 0; c < CIN; ++c)
        s = fmaf(xp[c * HWp], sw[c], s);

    g_mask[p] = (s > 0.0f) ? 1.0f : 0.0f;
}

// ---------------------------------------------------------------------------
// Kernel 2: mask_dilate = 3x3 maxpool(mask), SAME
// ---------------------------------------------------------------------------
__global__ void dilate_kernel()
{
    const int p  = blockIdx.x * 256 + threadIdx.x;
    const int n  = p >> 12;
    const int hw = p & 4095;
    const int h  = hw >> 6;
    const int w  = hw & 63;
    const float* m = g_mask + n * HWp;

    float v = 0.0f;
#pragma unroll
    for (int dy = -1; dy <= 1; ++dy) {
        const int hh = h + dy;
        if ((unsigned)hh >= (unsigned)HH) continue;
#pragma unroll
        for (int dx = -1; dx <= 1; ++dx) {
            const int ww = w + dx;
            if ((unsigned)ww >= (unsigned)WWp) continue;
            v = fmaxf(v, m[hh * WWp + ww]);
        }
    }
    g_maskd[p] = v;
}

// ---------------------------------------------------------------------------
// Kernel 3/4: 3x3 conv as implicit GEMM, 128x128x8 tiles, double-buffered smem.
//   EPI==0: in = x,     gate = mask_dilate, out = g_h1   (relu(conv*gate))
//   EPI==1: in = g_h1,  gate = mask,        out = d_out  (x + relu(conv*gate)*gate)
// ---------------------------------------------------------------------------
template <int EPI>
__global__ __launch_bounds__(256, 2)
void conv3x3_kernel(const float* __restrict__ xp,     // x (input for EPI=0, residual for EPI=1)
                    const float* __restrict__ wt,     // weights [256][2304] row-major
                    float* __restrict__ op)           // d_out (used when EPI=1)
{
    const float* xin  = (EPI == 0) ? xp : (const float*)g_h1;
    const float* gate = (EPI == 0) ? (const float*)g_maskd : (const float*)g_mask;
    float*       out  = (EPI == 0) ? (float*)g_h1 : op;

    __shared__ float As[2][BK][BM];
    __shared__ float Bs[2][BK][BN];

    const int t    = threadIdx.x;
    const int tx   = t & 15;          // pixel group (8 px)
    const int ty   = t >> 4;          // oc group (8 oc)
    const int pix0 = blockIdx.x * BN; // 128-pixel block: one image, two full rows
    const int oc0  = blockIdx.y * BM;
    const int n    = pix0 >> 12;
    const int hw0  = pix0 & 4095;
    const int h0   = hw0 >> 6;

    const float* xn = xin + n * (CIN * HWp);

    // A (weights) load mapping: thread -> one float4 of W row
    const int am = t >> 1;            // 0..127 : local oc
    const int ak = (t & 1) * 4;       // 0 or 4 : k offset within BK
    // B (im2col input) load mapping: thread -> 4 consecutive pixels of one k-row
    const int bk  = t >> 5;           // 0..7 : local k
    const int bp  = (t & 31) * 4;     // 0..124 : local pixel (4-aligned, same row)
    const int b_h = h0 + (bp >> 6);
    const int b_w = bp & 63;

    float acc[8][8];
#pragma unroll
    for (int i = 0; i < 8; ++i)
#pragma unroll
        for (int j = 0; j < 8; ++j) acc[i][j] = 0.0f;

    float4 areg;
    float  breg[4];

    // ---- load tile 0 ----
    {
        areg = *(const float4*)(wt + (oc0 + am) * KT + 0 + ak);
        const int kg = 0 + bk;
        const int c  = kg / 9;
        const int r  = kg - c * 9;
        const int ky = r / 3;
        const int dy = ky - 1;
        const int dx = (r - ky * 3) - 1;
        const int hh = b_h + dy;
        const bool rowok = (unsigned)hh < (unsigned)HH;
        const float* rowp = xn + c * HWp + hh * WWp;
#pragma unroll
        for (int j = 0; j < 4; ++j) {
            const int ww = b_w + dx + j;
            breg[j] = (rowok && (unsigned)ww < (unsigned)WWp) ? rowp[ww] : 0.0f;
        }
        As[0][ak + 0][am] = areg.x;
        As[0][ak + 1][am] = areg.y;
        As[0][ak + 2][am] = areg.z;
        As[0][ak + 3][am] = areg.w;
        *(float4*)&Bs[0][bk][bp] = make_float4(breg[0], breg[1], breg[2], breg[3]);
    }
    __syncthreads();

    int buf = 0;
    for (int kt = 0; kt < KTILES; ++kt) {
        const bool has_next = (kt + 1) < KTILES;
        if (has_next) {
            const int k0 = (kt + 1) * BK;
            areg = *(const float4*)(wt + (oc0 + am) * KT + k0 + ak);
            const int kg = k0 + bk;
            const int c  = kg / 9;
            const int r  = kg - c * 9;
            const int ky = r / 3;
            const int dy = ky - 1;
            const int dx = (r - ky * 3) - 1;
            const int hh = b_h + dy;
            const bool rowok = (unsigned)hh < (unsigned)HH;
            const float* rowp = xn + c * HWp + hh * WWp;
#pragma unroll
            for (int j = 0; j < 4; ++j) {
                const int ww = b_w + dx + j;
                breg[j] = (rowok && (unsigned)ww < (unsigned)WWp) ? rowp[ww] : 0.0f;
            }
        }

        // ---- compute on current buffer ----
#pragma unroll
        for (int k = 0; k < BK; ++k) {
            const float4 a0 = *(const float4*)&As[buf][k][ty * 8];
            const float4 a1 = *(const float4*)&As[buf][k][ty * 8 + 4];
            const float4 b0 = *(const float4*)&Bs[buf][k][tx * 8];
            const float4 b1 = *(const float4*)&Bs[buf][k][tx * 8 + 4];
            const float av[8] = {a0.x, a0.y, a0.z, a0.w, a1.x, a1.y, a1.z, a1.w};
            const float bv[8] = {b0.x, b0.y, b0.z, b0.w, b1.x, b1.y, b1.z, b1.w};
#pragma unroll
            for (int i = 0; i < 8; ++i)
#pragma unroll
                for (int j = 0; j < 8; ++j)
                    acc[i][j] = fmaf(av[i], bv[j], acc[i][j]);
        }

        if (has_next) {
            const int nb = buf ^ 1;
            As[nb][ak + 0][am] = areg.x;
            As[nb][ak + 1][am] = areg.y;
            As[nb][ak + 2][am] = areg.z;
            As[nb][ak + 3][am] = areg.w;
            *(float4*)&Bs[nb][bk][bp] = make_float4(breg[0], breg[1], breg[2], breg[3]);
        }
        __syncthreads();
        buf ^= 1;
    }

    // ---- epilogue ----
    const int pbase = hw0 + tx * 8;
    const float4 g0 = *(const float4*)(gate + pix0 + tx * 8);
    const float4 g1 = *(const float4*)(gate + pix0 + tx * 8 + 4);
    const float gv[8] = {g0.x, g0.y, g0.z, g0.w, g1.x, g1.y, g1.z, g1.w};

#pragma unroll
    for (int i = 0; i < 8; ++i) {
        const int oc = oc0 + ty * 8 + i;
        float* po = out + ((n * COUT + oc) * HWp + pbase);
        if (EPI == 0) {
            float4 v0, v1;
            v0.x = fmaxf(acc[i][0] * gv[0], 0.0f);
            v0.y = fmaxf(acc[i][1] * gv[1], 0.0f);
            v0.z = fmaxf(acc[i][2] * gv[2], 0.0f);
            v0.w = fmaxf(acc[i][3] * gv[3], 0.0f);
            v1.x = fmaxf(acc[i][4] * gv[4], 0.0f);
            v1.y = fmaxf(acc[i][5] * gv[5], 0.0f);
            v1.z = fmaxf(acc[i][6] * gv[6], 0.0f);
            v1.w = fmaxf(acc[i][7] * gv[7], 0.0f);
            *(float4*)po       = v0;
            *(float4*)(po + 4) = v1;
        } else {
            const float* pr = xp + ((n * CIN + oc) * HWp + pbase);
            const float4 r0 = *(const float4*)pr;
            const float4 r1 = *(const float4*)(pr + 4);
            float4 v0, v1;
            v0.x = r0.x + fmaxf(acc[i][0] * gv[0], 0.0f) * gv[0];
            v0.y = r0.y + fmaxf(acc[i][1] * gv[1], 0.0f) * gv[1];
            v0.z = r0.z + fmaxf(acc[i][2] * gv[2], 0.0f) * gv[2];
            v0.w = r0.w + fmaxf(acc[i][3] * gv[3], 0.0f) * gv[3];
            v1.x = r1.x + fmaxf(acc[i][4] * gv[4], 0.0f) * gv[4];
            v1.y = r1.y + fmaxf(acc[i][5] * gv[5], 0.0f) * gv[5];
            v1.z = r1.z + fmaxf(acc[i][6] * gv[6], 0.0f) * gv[6];
            v1.w = r1.w + fmaxf(acc[i][7] * gv[7], 0.0f) * gv[7];
            *(float4*)po       = v0;
            *(float4*)(po + 4) = v1;
        }
    }
}

// ---------------------------------------------------------------------------
extern "C" void kernel_launch(void* const* d_in, const int* in_sizes, int n_in,
                              void* d_out, int out_size)
{
    const float* x  = (const float*)d_in[0];   // [16,256,64,64]
    const float* w1 = (const float*)d_in[1];   // [256,256,3,3]
    const float* w2 = (const float*)d_in[2];   // [256,256,3,3]
    const float* wm = (const float*)d_in[3];   // [1,256,1,1]
    const float* bm = (const float*)d_in[4];   // [1]
    float* out = (float*)d_out;

    mask_kernel<<<NPIX / 256, 256>>>(x, wm, bm);
    dilate_kernel<<<NPIX / 256, 256>>>();

    dim3 grid(NPIX / BN, COUT / BM);           // (512, 2)
    conv3x3_kernel<0><<<grid, 256>>>(x, w1, out);   // -> g_h1 (out arg unused)
    conv3x3_kernel<1><<<grid, 256>>>(x, w2, out);   // g_h1 -> out, residual x
}

// round 12
// speedup vs baseline: 1.0052x; 1.0013x over previous
#include <cuda_runtime.h>
#include <cuda_bf16.h>

// Problem constants
constexpr int NB   = 16;
constexpr int CIN  = 256;
constexpr int COUT = 256;
constexpr int HH   = 64;
constexpr int WWp  = 64;
constexpr int HWp  = HH * WWp;          // 4096
constexpr int NPIX = NB * HWp;          // 65536
constexpr int KT   = CIN * 9;           // 2304

// GEMM tiling
constexpr int BM = 128;                 // out channels per block
constexpr int BN = 128;                 // pixels per block
constexpr int BK = 8;
constexpr int KTILES = KT / BK;         // 288

// Scratch (static device memory — no allocations)
__device__ float g_h1[NB * COUT * HWp];   // intermediate after conv1 (~67 MB)
__device__ float g_mask[NPIX];            // binary mask (std)
__device__ float g_maskd[NPIX];           // dilated mask (3x3 maxpool)

// ---------------------------------------------------------------------------
// Kernel 1: mask = (conv1x1(x, w_mask) + b > 0) ? 1 : 0
// ---------------------------------------------------------------------------
__global__ void mask_kernel(const float* __restrict__ x,
                            const float* __restrict__ wm,
                            const float* __restrict__ bm)
{
    __shared__ float sw[CIN];
    const int t = threadIdx.x;
    sw[t] = wm[t];
    __syncthreads();

    const int p  = blockIdx.x * 256 + t;     // 0..65535
    const int n  = p >> 12;
    const int hw = p & 4095;
    const float* xp = x + n * (CIN * HWp) + hw;

    float s = bm[0];
#pragma unroll 8
    for (int c = 0; c < CIN; ++c)
        s = fmaf(xp[c * HWp], sw[c], s);

    g_mask[p] = (s > 0.0f) ? 1.0f : 0.0f;
}

// ---------------------------------------------------------------------------
// Kernel 2: mask_dilate = 3x3 maxpool(mask), SAME
// ---------------------------------------------------------------------------
__global__ void dilate_kernel()
{
    const int p  = blockIdx.x * 256 + threadIdx.x;
    const int n  = p >> 12;
    const int hw = p & 4095;
    const int h  = hw >> 6;
    const int w  = hw & 63;
    const float* m = g_mask + n * HWp;

    float v = 0.0f;
#pragma unroll
    for (int dy = -1; dy <= 1; ++dy) {
        const int hh = h + dy;
        if ((unsigned)hh >= (unsigned)HH) continue;
#pragma unroll
        for (int dx = -1; dx <= 1; ++dx) {
            const int ww = w + dx;
            if ((unsigned)ww >= (unsigned)WWp) continue;
            v = fmaxf(v, m[hh * WWp + ww]);
        }
    }
    g_maskd[p] = v;
}

// ---------------------------------------------------------------------------
// Kernel 3/4: 3x3 conv as implicit GEMM, 128x128x8 tiles, double-buffered smem.
//   EPI==0: in = x,     gate = mask_dilate, out = g_h1   (relu(conv*gate))
//   EPI==1: in = g_h1,  gate = mask,        out = d_out  (x + relu(conv*gate)*gate)
// ---------------------------------------------------------------------------
template <int EPI>
__global__ __launch_bounds__(256, 2)
void conv3x3_kernel(const float* __restrict__ xp,     // x (input for EPI=0, residual for EPI=1)
                    const float* __restrict__ wt,     // weights [256][2304] row-major
                    float* __restrict__ op)           // d_out (used when EPI=1)
{
    const float* xin  = (EPI == 0) ? xp : (const float*)g_h1;
    const float* gate = (EPI == 0) ? (const float*)g_maskd : (const float*)g_mask;
    float*       out  = (EPI == 0) ? (float*)g_h1 : op;

    __shared__ float As[2][BK][BM];
    __shared__ float Bs[2][BK][BN];

    const int t    = threadIdx.x;
    const int tx   = t & 15;          // pixel group (8 px)
    const int ty   = t >> 4;          // oc group (8 oc)
    const int pix0 = blockIdx.x * BN; // 128-pixel block: one image, two full rows
    const int oc0  = blockIdx.y * BM;
    const int n    = pix0 >> 12;
    const int hw0  = pix0 & 4095;
    const int h0   = hw0 >> 6;

    const float* xn = xin + n * (CIN * HWp);

    // A (weights) load mapping: thread -> one float4 of W row
    const int am = t >> 1;            // 0..127 : local oc
    const int ak = (t & 1) * 4;       // 0 or 4 : k offset within BK
    // B (im2col input) load mapping: thread -> 4 consecutive pixels of one k-row
    const int bk  = t >> 5;           // 0..7 : local k
    const int bp  = (t & 31) * 4;     // 0..124 : local pixel (4-aligned, same row)
    const int b_h = h0 + (bp >> 6);
    const int b_w = bp & 63;

    float acc[8][8];
#pragma unroll
    for (int i = 0; i < 8; ++i)
#pragma unroll
        for (int j = 0; j < 8; ++j) acc[i][j] = 0.0f;

    float4 areg;
    float  breg[4];

    // ---- load tile 0 ----
    {
        areg = *(const float4*)(wt + (oc0 + am) * KT + 0 + ak);
        const int kg = 0 + bk;
        const int c  = kg / 9;
        const int r  = kg - c * 9;
        const int ky = r / 3;
        const int dy = ky - 1;
        const int dx = (r - ky * 3) - 1;
        const int hh = b_h + dy;
        const bool rowok = (unsigned)hh < (unsigned)HH;
        const float* rowp = xn + c * HWp + hh * WWp;
#pragma unroll
        for (int j = 0; j < 4; ++j) {
            const int ww = b_w + dx + j;
            breg[j] = (rowok && (unsigned)ww < (unsigned)WWp) ? rowp[ww] : 0.0f;
        }
        As[0][ak + 0][am] = areg.x;
        As[0][ak + 1][am] = areg.y;
        As[0][ak + 2][am] = areg.z;
        As[0][ak + 3][am] = areg.w;
        *(float4*)&Bs[0][bk][bp] = make_float4(breg[0], breg[1], breg[2], breg[3]);
    }
    __syncthreads();

    int buf = 0;
    for (int kt = 0; kt < KTILES; ++kt) {
        const bool has_next = (kt + 1) < KTILES;
        if (has_next) {
            const int k0 = (kt + 1) * BK;
            areg = *(const float4*)(wt + (oc0 + am) * KT + k0 + ak);
            const int kg = k0 + bk;
            const int c  = kg / 9;
            const int r  = kg - c * 9;
            const int ky = r / 3;
            const int dy = ky - 1;
            const int dx = (r - ky * 3) - 1;
            const int hh = b_h + dy;
            const bool rowok = (unsigned)hh < (unsigned)HH;
            const float* rowp = xn + c * HWp + hh * WWp;
#pragma unroll
            for (int j = 0; j < 4; ++j) {
                const int ww = b_w + dx + j;
                breg[j] = (rowok && (unsigned)ww < (unsigned)WWp) ? rowp[ww] : 0.0f;
            }
        }

        // ---- compute on current buffer ----
#pragma unroll
        for (int k = 0; k < BK; ++k) {
            const float4 a0 = *(const float4*)&As[buf][k][ty * 8];
            const float4 a1 = *(const float4*)&As[buf][k][ty * 8 + 4];
            const float4 b0 = *(const float4*)&Bs[buf][k][tx * 8];
            const float4 b1 = *(const float4*)&Bs[buf][k][tx * 8 + 4];
            const float av[8] = {a0.x, a0.y, a0.z, a0.w, a1.x, a1.y, a1.z, a1.w};
            const float bv[8] = {b0.x, b0.y, b0.z, b0.w, b1.x, b1.y, b1.z, b1.w};
#pragma unroll
            for (int i = 0; i < 8; ++i)
#pragma unroll
                for (int j = 0; j < 8; ++j)
                    acc[i][j] = fmaf(av[i], bv[j], acc[i][j]);
        }

        if (has_next) {
            const int nb = buf ^ 1;
            As[nb][ak + 0][am] = areg.x;
            As[nb][ak + 1][am] = areg.y;
            As[nb][ak + 2][am] = areg.z;
            As[nb][ak + 3][am] = areg.w;
            *(float4*)&Bs[nb][bk][bp] = make_float4(breg[0], breg[1], breg[2], breg[3]);
        }
        __syncthreads();
        buf ^= 1;
    }

    // ---- epilogue ----
    const int pbase = hw0 + tx * 8;
    const float4 g0 = *(const float4*)(gate + pix0 + tx * 8);
    const float4 g1 = *(const float4*)(gate + pix0 + tx * 8 + 4);
    const float gv[8] = {g0.x, g0.y, g0.z, g0.w, g1.x, g1.y, g1.z, g1.w};

#pragma unroll
    for (int i = 0; i < 8; ++i) {
        const int oc = oc0 + ty * 8 + i;
        float* po = out + ((n * COUT + oc) * HWp + pbase);
        if (EPI == 0) {
            float4 v0, v1;
            v0.x = fmaxf(acc[i][0] * gv[0], 0.0f);
            v0.y = fmaxf(acc[i][1] * gv[1], 0.0f);
            v0.z = fmaxf(acc[i][2] * gv[2], 0.0f);
            v0.w = fmaxf(acc[i][3] * gv[3], 0.0f);
            v1.x = fmaxf(acc[i][4] * gv[4], 0.0f);
            v1.y = fmaxf(acc[i][5] * gv[5], 0.0f);
            v1.z = fmaxf(acc[i][6] * gv[6], 0.0f);
            v1.w = fmaxf(acc[i][7] * gv[7], 0.0f);
            *(float4*)po       = v0;
            *(float4*)(po + 4) = v1;
        } else {
            const float* pr = xp + ((n * CIN + oc) * HWp + pbase);
            const float4 r0 = *(const float4*)pr;
            const float4 r1 = *(const float4*)(pr + 4);
            float4 v0, v1;
            v0.x = r0.x + fmaxf(acc[i][0] * gv[0], 0.0f) * gv[0];
            v0.y = r0.y + fmaxf(acc[i][1] * gv[1], 0.0f) * gv[1];
            v0.z = r0.z + fmaxf(acc[i][2] * gv[2], 0.0f) * gv[2];
            v0.w = r0.w + fmaxf(acc[i][3] * gv[3], 0.0f) * gv[3];
            v1.x = r1.x + fmaxf(acc[i][4] * gv[4], 0.0f) * gv[4];
            v1.y = r1.y + fmaxf(acc[i][5] * gv[5], 0.0f) * gv[5];
            v1.z = r1.z + fmaxf(acc[i][6] * gv[6], 0.0f) * gv[6];
            v1.w = r1.w + fmaxf(acc[i][7] * gv[7], 0.0f) * gv[7];
            *(float4*)po       = v0;
            *(float4*)(po + 4) = v1;
        }
    }
}

// ---------------------------------------------------------------------------
extern "C" void kernel_launch(void* const* d_in, const int* in_sizes, int n_in,
                              void* d_out, int out_size)
{
    const float* x  = (const float*)d_in[0];   // [16,256,64,64]
    const float* w1 = (const float*)d_in[1];   // [256,256,3,3]
    const float* w2 = (const float*)d_in[2];   // [256,256,3,3]
    const float* wm = (const float*)d_in[3];   // [1,256,1,1]
    const float* bm = (const float*)d_in[4];   // [1]
    float* out = (float*)d_out;

    mask_kernel<<<NPIX / 256, 256>>>(x, wm, bm);
    dilate_kernel<<<NPIX / 256, 256>>>();

    dim3 grid(NPIX / BN, COUT / BM);           // (512, 2)
    conv3x3_kernel<0><<<grid, 256>>>(x, w1, out);   // -> g_h1 (out arg unused)
    conv3x3_kernel<1><<<grid, 256>>>(x, w2, out);   // g_h1 -> out, residual x
}